// round 9
// baseline (speedup 1.0000x reference)
#include <cuda_runtime.h>
#include <cuda_bf16.h>
#include <math.h>
#include <stdint.h>

// Problem constants
#define S_LEN   2048
#define DMODEL  2048
#define NHEADS  16
#define DKH     128
#define BATCH   4
#define BHN     (BATCH * NHEADS)   // 64
#define E3      (3 * DMODEL)       // 6144
#define MROWS   (BATCH * S_LEN)    // 8192
#define KDIM    DMODEL             // 2048
#define KW      (KDIM / 2)         // 1024 packed uint32 per row

// ---------------------------------------------------------------------------
// Scratch (static device globals: allocation-free rule)
// ---------------------------------------------------------------------------
__device__ __align__(256) float g_q[BHN * S_LEN * DKH];
__device__ __align__(256) float g_k[BHN * S_LEN * DKH];
__device__ __align__(256) float g_v[BHN * S_LEN * DKH];
__device__ __align__(256) float g_attn[BATCH * S_LEN * DMODEL];
__device__ __align__(256) float g_cos[S_LEN * (DKH / 2)];
__device__ __align__(256) float g_sin[S_LEN * (DKH / 2)];

// packed bf16-pair operands (uint32 = {lo16: even k, hi16: odd k})
__device__ __align__(256) uint32_t g_xp_h[MROWS * KW];
__device__ __align__(256) uint32_t g_xp_l[MROWS * KW];
__device__ __align__(256) uint32_t g_wq_h[E3 * KW];
__device__ __align__(256) uint32_t g_wq_l[E3 * KW];
__device__ __align__(256) uint32_t g_wo_h[DMODEL * KW];
__device__ __align__(256) uint32_t g_wo_l[DMODEL * KW];
__device__ __align__(256) uint32_t g_ap_h[MROWS * KW];
__device__ __align__(256) uint32_t g_ap_l[MROWS * KW];

__device__ int g_flag[2];   // [0]=QKV HMMA bad, [1]=out-proj HMMA bad

// ---------------------------------------------------------------------------
// helpers
// ---------------------------------------------------------------------------
__device__ __forceinline__ uint32_t pack_bf16x2(float a, float b) {
    return (uint32_t)__bfloat16_as_ushort(__float2bfloat16(a)) |
           ((uint32_t)__bfloat16_as_ushort(__float2bfloat16(b)) << 16);
}
__device__ __forceinline__ float bf16_res(float f) {
    return f - __bfloat162float(__float2bfloat16(f));
}
__device__ __forceinline__ uint32_t smem_to_u32(const void* p) {
    uint32_t a;
    asm("{ .reg .u64 t; cvta.to.shared.u64 t, %1; cvt.u32.u64 %0, t; }" : "=r"(a) : "l"(p));
    return a;
}
__device__ __forceinline__ void cp_async16(uint32_t smem, const void* g) {
    asm volatile("cp.async.cg.shared.global [%0], [%1], 16;" :: "r"(smem), "l"(g) : "memory");
}
#define CP_COMMIT() asm volatile("cp.async.commit_group;" ::: "memory")
#define CP_WAIT(n)  asm volatile("cp.async.wait_group %0;" :: "n"(n) : "memory")

__device__ __forceinline__ void ldx4(uint32_t* r, uint32_t addr) {
    asm volatile("ldmatrix.sync.aligned.m8n8.x4.shared.b16 {%0,%1,%2,%3}, [%4];"
                 : "=r"(r[0]), "=r"(r[1]), "=r"(r[2]), "=r"(r[3]) : "r"(addr));
}
__device__ __forceinline__ void mma16816(float* d, const uint32_t* a, const uint32_t* b) {
    asm volatile(
        "mma.sync.aligned.m16n8k16.row.col.f32.bf16.bf16.f32 "
        "{%0,%1,%2,%3}, {%4,%5,%6,%7}, {%8,%9}, {%0,%1,%2,%3};"
        : "+f"(d[0]), "+f"(d[1]), "+f"(d[2]), "+f"(d[3])
        : "r"(a[0]), "r"(a[1]), "r"(a[2]), "r"(a[3]), "r"(b[0]), "r"(b[1]));
}

// ---------------------------------------------------------------------------
// flags / RoPE tables / RoPE apply / split
// ---------------------------------------------------------------------------
__global__ void zero_flags_kernel() { g_flag[0] = 0; g_flag[1] = 0; }

__global__ void rope_tables_kernel() {
    int idx = blockIdx.x * blockDim.x + threadIdx.x;
    if (idx >= S_LEN * (DKH / 2)) return;
    int i = idx % (DKH / 2);
    int s = idx / (DKH / 2);
    double inv = exp(-((double)(2 * i) / (double)DKH) * log(10000.0));
    double ang = (double)s * inv;
    g_cos[idx] = (float)cos(ang);
    g_sin[idx] = (float)sin(ang);
}

__global__ void rope_apply_kernel() {
    int idx = blockIdx.x * blockDim.x + threadIdx.x;
    int i  = idx & 63;
    int s  = (idx >> 6) & (S_LEN - 1);
    int bh = idx >> 17;
    if (bh >= BHN) return;
    float cs = g_cos[(s << 6) + i];
    float sn = g_sin[(s << 6) + i];
    size_t base = (((size_t)bh * S_LEN + s) << 7) + (i << 1);
    float2 q = *(float2*)&g_q[base];
    float2 k = *(float2*)&g_k[base];
    float2 qo = make_float2(q.x * cs - q.y * sn, q.x * sn + q.y * cs);
    float2 ko = make_float2(k.x * cs - k.y * sn, k.x * sn + k.y * cs);
    *(float2*)&g_q[base] = qo;
    *(float2*)&g_k[base] = ko;
}

__global__ void split_pack_kernel(const float* __restrict__ src,
                                  uint32_t* __restrict__ hi,
                                  uint32_t* __restrict__ lo, int n4) {
    int i = blockIdx.x * blockDim.x + threadIdx.x;
    if (i >= n4) return;
    float4 v = ((const float4*)src)[i];
    uint2 h = make_uint2(pack_bf16x2(v.x, v.y), pack_bf16x2(v.z, v.w));
    uint2 l = make_uint2(pack_bf16x2(bf16_res(v.x), bf16_res(v.y)),
                         pack_bf16x2(bf16_res(v.z), bf16_res(v.w)));
    ((uint2*)hi)[i] = h;
    ((uint2*)lo)[i] = l;
}

// ---------------------------------------------------------------------------
// HMMA bf16 split-GEMM (R3 structure: ldmatrix + cp.async 2-stage).
// C[M,N] = A[M,K]*B[N,K]^T;  3 products: Ah*Bh + Ah*Bl + Al*Bh.
// CTA 128x128, 8 warps (2x4), warp 64x32, K-chunk 32 bf16 (16 uint32).
// MODE 1: QKV -> scatter g_q/g_k/g_v.  MODE 2: out-proj -> row-major C.
// ---------------------------------------------------------------------------
#define ROWB 80                     // smem row pitch (64B data + 16B pad)
#define MAT_BYTES (128 * ROWB)      // 10240
#define OFF_AH 0
#define OFF_AL MAT_BYTES
#define OFF_BH (2 * MAT_BYTES)
#define OFF_BL (3 * MAT_BYTES)
#define STAGE_BYTES (4 * MAT_BYTES) // 40960
#define GEMM_SMEM (2 * STAGE_BYTES) // 81920
#define NKC (KDIM / 32)             // 64

template <int MODE>
__global__ void __launch_bounds__(256)
gemm_hmma(const uint32_t* __restrict__ Ahg, const uint32_t* __restrict__ Alg,
          const uint32_t* __restrict__ Bhg, const uint32_t* __restrict__ Blg,
          float* __restrict__ C) {
    extern __shared__ char sm[];
    const uint32_t sbase = smem_to_u32(sm);
    const int tid = threadIdx.x;
    const int lane = tid & 31;
    const int wid = tid >> 5;
    const int warp_m = wid >> 2;      // 0..1
    const int warp_n = wid & 3;       // 0..3
    const int bm = blockIdx.y << 7;
    const int bn = blockIdx.x << 7;

    // loader: idx -> row = idx>>2 (0..127), chunk = idx&3 (16B each)
    const int lrow0 = tid >> 2;
    const int lch = tid & 3;

    float acc[4][4][4];
#pragma unroll
    for (int i = 0; i < 4; i++)
#pragma unroll
        for (int j = 0; j < 4; j++)
#pragma unroll
            for (int t = 0; t < 4; t++) acc[i][j][t] = 0.0f;

    // prologue: prefetch stages kc=0,1 (chunk of 16 uint32 per row per kc)
#pragma unroll
    for (int p = 0; p < 2; p++) {
        const int kb = p << 4;   // word offset
        const uint32_t st = sbase + p * STAGE_BYTES;
#pragma unroll
        for (int it = 0; it < 2; it++) {
            int row = lrow0 + (it << 6);
            uint32_t so = row * ROWB + (lch << 4);
            size_t ga = (size_t)(bm + row) * KW + kb + (lch << 2);
            size_t gb = (size_t)(bn + row) * KW + kb + (lch << 2);
            cp_async16(st + OFF_AH + so, Ahg + ga);
            cp_async16(st + OFF_AL + so, Alg + ga);
            cp_async16(st + OFF_BH + so, Bhg + gb);
            cp_async16(st + OFF_BL + so, Blg + gb);
        }
        CP_COMMIT();
    }

    // ldmatrix base offsets (within one matrix region)
    const uint32_t a_off0 = (uint32_t)((warp_m * 64 + (lane & 15)) * ROWB + ((lane >> 4) << 4));
    const uint32_t b_off0 = (uint32_t)((warp_n * 32 + (lane & 7) + ((lane >> 4) << 3)) * ROWB
                                       + (((lane >> 3) & 1) << 4));

    for (int kc = 0; kc < NKC; kc++) {
        const int buf = kc & 1;
        if (kc == NKC - 1) { CP_WAIT(0); } else { CP_WAIT(1); }
        __syncthreads();

        const uint32_t st = sbase + buf * STAGE_BYTES;
#pragma unroll
        for (int k16 = 0; k16 < 2; k16++) {
            uint32_t ah[4][4], al[4][4], bH[4][2], bL[4][2];
            const uint32_t kadd = (uint32_t)(k16 << 5);  // 16 bf16 = 32 bytes
#pragma unroll
            for (int mf = 0; mf < 4; mf++) {
                uint32_t ad = st + a_off0 + kadd + (uint32_t)(mf * 16 * ROWB);
                ldx4(ah[mf], ad + OFF_AH);
                ldx4(al[mf], ad + OFF_AL);
            }
#pragma unroll
            for (int nq = 0; nq < 2; nq++) {
                uint32_t bd = st + b_off0 + kadd + (uint32_t)(nq * 16 * ROWB);
                uint32_t rh[4], rl[4];
                ldx4(rh, bd + OFF_BH);
                ldx4(rl, bd + OFF_BL);
                bH[nq * 2][0] = rh[0]; bH[nq * 2][1] = rh[1];
                bH[nq * 2 + 1][0] = rh[2]; bH[nq * 2 + 1][1] = rh[3];
                bL[nq * 2][0] = rl[0]; bL[nq * 2][1] = rl[1];
                bL[nq * 2 + 1][0] = rl[2]; bL[nq * 2 + 1][1] = rl[3];
            }
#pragma unroll
            for (int mf = 0; mf < 4; mf++)
#pragma unroll
                for (int nn = 0; nn < 4; nn++) {
                    mma16816(acc[mf][nn], ah[mf], bH[nn]);
                    mma16816(acc[mf][nn], ah[mf], bL[nn]);
                    mma16816(acc[mf][nn], al[mf], bH[nn]);
                }
        }
        __syncthreads();

        // prefetch kc+2 into this buffer
        if (kc + 2 < NKC) {
            const int kb = (kc + 2) << 4;
            const uint32_t stw = sbase + buf * STAGE_BYTES;
#pragma unroll
            for (int it = 0; it < 2; it++) {
                int row = lrow0 + (it << 6);
                uint32_t so = row * ROWB + (lch << 4);
                size_t ga = (size_t)(bm + row) * KW + kb + (lch << 2);
                size_t gb = (size_t)(bn + row) * KW + kb + (lch << 2);
                cp_async16(stw + OFF_AH + so, Ahg + ga);
                cp_async16(stw + OFF_AL + so, Alg + ga);
                cp_async16(stw + OFF_BH + so, Bhg + gb);
                cp_async16(stw + OFF_BL + so, Blg + gb);
            }
            CP_COMMIT();
        }
    }

    // epilogue: D fragment (quad, 2*qi)
    const int quad = lane >> 2, qi = lane & 3;
    const int rbase = bm + warp_m * 64 + quad;
    const int cbase = warp_n * 32 + qi * 2;
#pragma unroll
    for (int mf = 0; mf < 4; mf++) {
#pragma unroll
        for (int nn = 0; nn < 4; nn++) {
            int col = cbase + nn * 8;
            int r0 = rbase + mf * 16;
            int r1 = r0 + 8;
            if (MODE == 2) {
                float* p0 = C + (size_t)r0 * DMODEL + bn + col;
                float* p1 = C + (size_t)r1 * DMODEL + bn + col;
                *(float2*)p0 = make_float2(acc[mf][nn][0], acc[mf][nn][1]);
                *(float2*)p1 = make_float2(acc[mf][nn][2], acc[mf][nn][3]);
            } else {
                const int part = bn >> 11;
                const int h = (bn >> 7) & 15;
                float* dst = (part == 0) ? g_q : ((part == 1) ? g_k : g_v);
                int b0 = r0 >> 11, s0 = r0 & (S_LEN - 1);
                int b1 = r1 >> 11, s1 = r1 & (S_LEN - 1);
                float* p0 = dst + (((size_t)(b0 * NHEADS + h) * S_LEN + s0) << 7) + col;
                float* p1 = dst + (((size_t)(b1 * NHEADS + h) * S_LEN + s1) << 7) + col;
                *(float2*)p0 = make_float2(acc[mf][nn][0], acc[mf][nn][1]);
                *(float2*)p1 = make_float2(acc[mf][nn][2], acc[mf][nn][3]);
            }
        }
    }
}

// ---------------------------------------------------------------------------
// FFMA SGEMM (R1-validated), templated:
//   ACT 1 = CHECK: compare vs HMMA result, set g_flag[MODE-1]
//   ACT 2 = FALLBACK: early-exit if flag clean, else compute+store
// Tolerance: 10x above split noise (~2.4e-4 abs), far below real-bug errors.
// ---------------------------------------------------------------------------
#define CHK_TOL(ref) (5e-3f * fabsf(ref) + 1e-3f)

template <int MODE, int ACT>
__global__ void __launch_bounds__(256, 2)
sgemm_nt(const float* __restrict__ A, const float* __restrict__ Bw,
         float* __restrict__ C, int M, int N, int K) {
    if (ACT == 2 && g_flag[MODE - 1] == 0) return;

    __shared__ float As[8 * 132];
    __shared__ float Bs[8 * 132];

    const int bm = blockIdx.y << 7;
    const int bn = blockIdx.x << 7;
    const int tid = threadIdx.x;
    const int tx = tid & 15, ty = tid >> 4;

    const float* Aarr = (MODE == 2) ? g_attn : A;
    const int lr = tid >> 1;
    const int lk = (tid & 1) << 2;
    const float* Ap = Aarr + (size_t)(bm + lr) * K + lk;
    const float* Bp = Bw + (size_t)(bn + lr) * K + lk;

    float acc[8][8];
#pragma unroll
    for (int i = 0; i < 8; i++)
#pragma unroll
        for (int j = 0; j < 8; j++) acc[i][j] = 0.0f;

    float4 af = *(const float4*)Ap;
    float4 bf = *(const float4*)Bp;

    for (int k0 = 0; k0 < K; k0 += 8) {
        __syncthreads();
        As[(lk + 0) * 132 + lr] = af.x;
        As[(lk + 1) * 132 + lr] = af.y;
        As[(lk + 2) * 132 + lr] = af.z;
        As[(lk + 3) * 132 + lr] = af.w;
        Bs[(lk + 0) * 132 + lr] = bf.x;
        Bs[(lk + 1) * 132 + lr] = bf.y;
        Bs[(lk + 2) * 132 + lr] = bf.z;
        Bs[(lk + 3) * 132 + lr] = bf.w;
        __syncthreads();
        if (k0 + 8 < K) {
            af = *(const float4*)(Ap + k0 + 8);
            bf = *(const float4*)(Bp + k0 + 8);
        }
#pragma unroll
        for (int kk = 0; kk < 8; kk++) {
            float a[8], b[8];
            *(float4*)(a)     = *(const float4*)&As[kk * 132 + (ty << 3)];
            *(float4*)(a + 4) = *(const float4*)&As[kk * 132 + (ty << 3) + 4];
            *(float4*)(b)     = *(const float4*)&Bs[kk * 132 + (tx << 3)];
            *(float4*)(b + 4) = *(const float4*)&Bs[kk * 132 + (tx << 3) + 4];
#pragma unroll
            for (int i = 0; i < 8; i++)
#pragma unroll
                for (int j = 0; j < 8; j++)
                    acc[i][j] = fmaf(a[i], b[j], acc[i][j]);
        }
    }

    int bad = 0;
    if (MODE == 2) {
#pragma unroll
        for (int i = 0; i < 8; i++) {
            float* crow = C + (size_t)(bm + (ty << 3) + i) * N + bn + (tx << 3);
            if (ACT == 1) {
#pragma unroll
                for (int j = 0; j < 8; j++)
                    if (fabsf(acc[i][j] - crow[j]) > CHK_TOL(acc[i][j])) bad++;
            } else {
                *(float4*)(crow)     = make_float4(acc[i][0], acc[i][1], acc[i][2], acc[i][3]);
                *(float4*)(crow + 4) = make_float4(acc[i][4], acc[i][5], acc[i][6], acc[i][7]);
            }
        }
    } else {
        const int part = bn >> 11;
        const int h = (bn >> 7) & 15;
        const int dkbase = (bn & 127) + (tx << 3);
        float* dst = (part == 0) ? g_q : ((part == 1) ? g_k : g_v);
#pragma unroll
        for (int i = 0; i < 8; i++) {
            int m = bm + (ty << 3) + i;
            int b = m >> 11;
            int s = m & (S_LEN - 1);
            float* row = dst + (((size_t)(b * NHEADS + h) * S_LEN + s) << 7) + dkbase;
            if (ACT == 1) {
#pragma unroll
                for (int j = 0; j < 8; j++)
                    if (fabsf(acc[i][j] - row[j]) > CHK_TOL(acc[i][j])) bad++;
            } else {
                *(float4*)(row)     = make_float4(acc[i][0], acc[i][1], acc[i][2], acc[i][3]);
                *(float4*)(row + 4) = make_float4(acc[i][4], acc[i][5], acc[i][6], acc[i][7]);
            }
        }
    }
    if (ACT == 1 && bad > 0) atomicAdd(&g_flag[MODE - 1], bad);
}

// ---------------------------------------------------------------------------
// R1-validated flash attention (causal, fp32) -> g_attn
// ---------------------------------------------------------------------------
#define ATTN_SMEM_FLOATS (3 * 64 * 132 + 64 * 68)

__global__ void __launch_bounds__(256)
attn_kernel() {
    extern __shared__ float smf[];
    float* Qs = smf;
    float* Ks = smf + 64 * 132;
    float* Vs = smf + 2 * 64 * 132;
    float* Ps = smf + 3 * 64 * 132;

    const int qt = blockIdx.x;
    const int bh = blockIdx.y;
    const size_t base = (size_t)bh * S_LEN * DKH;
    const float* qp = g_q + base + ((size_t)qt << 6) * DKH;
    const float* kp = g_k + base;
    const float* vp = g_v + base;

    const int tid = threadIdx.x;
    const int tx = tid & 15, ty = tid >> 4;
    const int r0 = ty << 2;
    const int c0 = tx << 2;
    const int cv = tx << 3;

    for (int i = tid; i < 64 * 32; i += 256) {
        int r = i >> 5, c4 = (i & 31) << 2;
        *(float4*)&Qs[r * 132 + c4] = *(const float4*)&qp[r * 128 + c4];
    }

    float o[4][8];
#pragma unroll
    for (int i = 0; i < 4; i++)
#pragma unroll
        for (int c = 0; c < 8; c++) o[i][c] = 0.0f;
    float mi[4] = {-INFINITY, -INFINITY, -INFINITY, -INFINITY};
    float li[4] = {0.0f, 0.0f, 0.0f, 0.0f};
    const float scale = 0.08838834764831845f;

    for (int j = 0; j <= qt; j++) {
        __syncthreads();
        const float* kt = kp + ((size_t)j << 6) * DKH;
        const float* vt = vp + ((size_t)j << 6) * DKH;
        for (int i = tid; i < 64 * 32; i += 256) {
            int r = i >> 5, c4 = (i & 31) << 2;
            *(float4*)&Ks[r * 132 + c4] = *(const float4*)&kt[r * 128 + c4];
            *(float4*)&Vs[r * 132 + c4] = *(const float4*)&vt[r * 128 + c4];
        }
        __syncthreads();

        float s[4][4];
#pragma unroll
        for (int i = 0; i < 4; i++)
#pragma unroll
            for (int ii = 0; ii < 4; ii++) s[i][ii] = 0.0f;

#pragma unroll 4
        for (int k4 = 0; k4 < 32; k4++) {
            float q[4][4], kv[4][4];
#pragma unroll
            for (int i = 0; i < 4; i++)
                *(float4*)q[i] = *(const float4*)&Qs[(r0 + i) * 132 + (k4 << 2)];
#pragma unroll
            for (int ii = 0; ii < 4; ii++)
                *(float4*)kv[ii] = *(const float4*)&Ks[(c0 + ii) * 132 + (k4 << 2)];
#pragma unroll
            for (int i = 0; i < 4; i++)
#pragma unroll
                for (int ii = 0; ii < 4; ii++)
#pragma unroll
                    for (int t = 0; t < 4; t++)
                        s[i][ii] = fmaf(q[i][t], kv[ii][t], s[i][ii]);
        }

#pragma unroll
        for (int i = 0; i < 4; i++) {
            float sv[4];
#pragma unroll
            for (int ii = 0; ii < 4; ii++) {
                float v = s[i][ii] * scale;
                if (j == qt && (c0 + ii) > (r0 + i)) v = -1e30f;
                sv[ii] = v;
            }
            float rm = fmaxf(fmaxf(sv[0], sv[1]), fmaxf(sv[2], sv[3]));
#pragma unroll
            for (int off = 8; off >= 1; off >>= 1)
                rm = fmaxf(rm, __shfl_xor_sync(0xffffffffu, rm, off));
            float mn = fmaxf(mi[i], rm);
            float al = __expf(mi[i] - mn);
            float rs = 0.0f;
#pragma unroll
            for (int ii = 0; ii < 4; ii++) {
                float p = __expf(sv[ii] - mn);
                sv[ii] = p;
                rs += p;
            }
#pragma unroll
            for (int off = 8; off >= 1; off >>= 1)
                rs += __shfl_xor_sync(0xffffffffu, rs, off);
            li[i] = li[i] * al + rs;
            mi[i] = mn;
#pragma unroll
            for (int c = 0; c < 8; c++) o[i][c] *= al;
            *(float4*)&Ps[(r0 + i) * 68 + c0] = make_float4(sv[0], sv[1], sv[2], sv[3]);
        }
        __syncthreads();

#pragma unroll 4
        for (int jj4 = 0; jj4 < 16; jj4++) {
            float p[4][4];
#pragma unroll
            for (int i = 0; i < 4; i++)
                *(float4*)p[i] = *(const float4*)&Ps[(r0 + i) * 68 + (jj4 << 2)];
#pragma unroll
            for (int t = 0; t < 4; t++) {
                int jj = (jj4 << 2) + t;
                float v[8];
                *(float4*)(v)     = *(const float4*)&Vs[jj * 132 + cv];
                *(float4*)(v + 4) = *(const float4*)&Vs[jj * 132 + cv + 4];
#pragma unroll
                for (int i = 0; i < 4; i++)
#pragma unroll
                    for (int c = 0; c < 8; c++)
                        o[i][c] = fmaf(p[i][t], v[c], o[i][c]);
            }
        }
    }

    const int b = bh >> 4, h = bh & 15;
#pragma unroll
    for (int i = 0; i < 4; i++) {
        float inv = 1.0f / li[i];
        int srow = (qt << 6) + r0 + i;
        float* orow = g_attn + (((size_t)(b * S_LEN + srow)) << 11) + (h << 7) + cv;
        *(float4*)(orow)     = make_float4(o[i][0] * inv, o[i][1] * inv, o[i][2] * inv, o[i][3] * inv);
        *(float4*)(orow + 4) = make_float4(o[i][4] * inv, o[i][5] * inv, o[i][6] * inv, o[i][7] * inv);
    }
}

// ---------------------------------------------------------------------------
// kernel_launch
// ---------------------------------------------------------------------------
extern "C" void kernel_launch(void* const* d_in, const int* in_sizes, int n_in,
                              void* d_out, int out_size) {
    const float* x     = (const float*)d_in[0];
    const float* w_qkv = (const float*)d_in[1];
    const float* w_out = (const float*)d_in[2];
    float* out = (float*)d_out;

    cudaFuncSetAttribute(attn_kernel, cudaFuncAttributeMaxDynamicSharedMemorySize,
                         ATTN_SMEM_FLOATS * (int)sizeof(float));
    cudaFuncSetAttribute(gemm_hmma<1>, cudaFuncAttributeMaxDynamicSharedMemorySize,
                         GEMM_SMEM);
    cudaFuncSetAttribute(gemm_hmma<2>, cudaFuncAttributeMaxDynamicSharedMemorySize,
                         GEMM_SMEM);

    zero_flags_kernel<<<1, 1>>>();
    rope_tables_kernel<<<(S_LEN * (DKH / 2) + 255) / 256, 256>>>();

    // splits (packed uint32 hi/lo)
    split_pack_kernel<<<(MROWS * KDIM / 4) / 256, 256>>>(x, g_xp_h, g_xp_l,
                                                         MROWS * KDIM / 4);
    split_pack_kernel<<<(E3 * KDIM / 4) / 256, 256>>>(w_qkv, g_wq_h, g_wq_l,
                                                      E3 * KDIM / 4);
    split_pack_kernel<<<(DMODEL * KDIM / 4) / 256, 256>>>(w_out, g_wo_h, g_wo_l,
                                                          DMODEL * KDIM / 4);

    // QKV projection (HMMA) -> g_q/g_k/g_v, check slice, gated fallback
    gemm_hmma<1><<<dim3(E3 / 128, MROWS / 128), 256, GEMM_SMEM>>>(
        g_xp_h, g_xp_l, g_wq_h, g_wq_l, nullptr);
    sgemm_nt<1, 1><<<dim3(E3 / 128, 2), 256>>>(x, w_qkv, nullptr, MROWS, E3, KDIM);
    sgemm_nt<1, 2><<<dim3(E3 / 128, MROWS / 128), 256>>>(x, w_qkv, nullptr,
                                                         MROWS, E3, KDIM);

    // RoPE in place on q,k
    rope_apply_kernel<<<(BHN * S_LEN * 64) / 256, 256>>>();

    // causal flash attention (fp32) -> g_attn
    attn_kernel<<<dim3(S_LEN / 64, BHN), 256,
                  ATTN_SMEM_FLOATS * (int)sizeof(float)>>>();

    // out-projection (HMMA) -> d_out, check slice, gated fallback
    split_pack_kernel<<<(MROWS * DMODEL / 4) / 256, 256>>>(g_attn, g_ap_h, g_ap_l,
                                                           MROWS * DMODEL / 4);
    gemm_hmma<2><<<dim3(DMODEL / 128, MROWS / 128), 256, GEMM_SMEM>>>(
        g_ap_h, g_ap_l, g_wo_h, g_wo_l, out);
    sgemm_nt<2, 1><<<dim3(DMODEL / 128, 2), 256>>>(nullptr, w_out, out,
                                                   MROWS, DMODEL, KDIM);
    sgemm_nt<2, 2><<<dim3(DMODEL / 128, MROWS / 128), 256>>>(nullptr, w_out, out,
                                                             MROWS, DMODEL, KDIM);
}

// round 10
// speedup vs baseline: 7.4359x; 7.4359x over previous
#include <cuda_runtime.h>
#include <math.h>
#include <stdint.h>

// Problem constants
#define S_LEN   2048
#define DMODEL  2048
#define NHEADS  16
#define DKH     128
#define BATCH   4
#define BHN     (BATCH * NHEADS)   // 64
#define E3      (3 * DMODEL)       // 6144
#define MROWS   (BATCH * S_LEN)    // 8192
#define KDIM    DMODEL             // 2048

// ---------------------------------------------------------------------------
// Scratch (static device globals: allocation-free rule)
// ---------------------------------------------------------------------------
__device__ __align__(256) float g_q[BHN * S_LEN * DKH];
__device__ __align__(256) float g_k[BHN * S_LEN * DKH];
__device__ __align__(256) float g_v[BHN * S_LEN * DKH];
__device__ __align__(256) float g_attn[BATCH * S_LEN * DMODEL];
__device__ __align__(256) float g_cos[S_LEN * (DKH / 2)];
__device__ __align__(256) float g_sin[S_LEN * (DKH / 2)];

// ---------------------------------------------------------------------------
// helpers
// ---------------------------------------------------------------------------
__device__ __forceinline__ uint32_t smem_to_u32(const void* p) {
    uint32_t a;
    asm("{ .reg .u64 t; cvta.to.shared.u64 t, %1; cvt.u32.u64 %0, t; }" : "=r"(a) : "l"(p));
    return a;
}
__device__ __forceinline__ void cp_async16(uint32_t smem, const void* g) {
    asm volatile("cp.async.cg.shared.global [%0], [%1], 16;" :: "r"(smem), "l"(g) : "memory");
}
#define CP_COMMIT() asm volatile("cp.async.commit_group;" ::: "memory")
#define CP_WAIT(n)  asm volatile("cp.async.wait_group %0;" :: "n"(n) : "memory")

// ---------------------------------------------------------------------------
// RoPE tables (fp64 for accuracy)
// ---------------------------------------------------------------------------
__global__ void rope_tables_kernel() {
    int idx = blockIdx.x * blockDim.x + threadIdx.x;
    if (idx >= S_LEN * (DKH / 2)) return;
    int i = idx % (DKH / 2);
    int s = idx / (DKH / 2);
    double inv = exp(-((double)(2 * i) / (double)DKH) * log(10000.0));
    double ang = (double)s * inv;
    g_cos[idx] = (float)cos(ang);
    g_sin[idx] = (float)sin(ang);
}

// ---------------------------------------------------------------------------
// FFMA SGEMM, k-tile 16, double-buffered smem (ONE barrier per chunk),
// register prefetch.  C[M,N] = A[M,K] * B[N,K]^T.
// MODE 1: QKV -> scatter g_q/g_k/g_v with RoPE fused on q,k parts.
// MODE 2: out-proj (A = g_attn) -> row-major C.
// ---------------------------------------------------------------------------
template <int MODE>
__global__ void __launch_bounds__(256, 2)
sgemm16_nt(const float* __restrict__ A, const float* __restrict__ Bw,
           float* __restrict__ C, int M, int N, int K) {
    __shared__ float As[2][16 * 132];
    __shared__ float Bs[2][16 * 132];

    const int bm = blockIdx.y << 7;
    const int bn = blockIdx.x << 7;
    const int tid = threadIdx.x;
    const int tx = tid & 15, ty = tid >> 4;

    const float* Aarr = (MODE == 2) ? g_attn : A;
    const int lr = tid >> 1;            // row 0..127
    const int lk = (tid & 1) << 2;      // k offset 0 or 4
    const float* Ap = Aarr + (size_t)(bm + lr) * K + lk;
    const float* Bp = Bw + (size_t)(bn + lr) * K + lk;

    float acc[8][8];
#pragma unroll
    for (int i = 0; i < 8; i++)
#pragma unroll
        for (int j = 0; j < 8; j++) acc[i][j] = 0.0f;

    // prefetch chunk 0: k positions lk..lk+3 and lk+8..lk+11
    float4 a0 = *(const float4*)Ap;
    float4 a1 = *(const float4*)(Ap + 8);
    float4 b0 = *(const float4*)Bp;
    float4 b1 = *(const float4*)(Bp + 8);

    const int NCH = K >> 4;   // 128
    for (int c = 0; c < NCH; c++) {
        const int buf = c & 1;
        float* as = As[buf];
        float* bs = Bs[buf];
        as[(lk + 0) * 132 + lr] = a0.x;
        as[(lk + 1) * 132 + lr] = a0.y;
        as[(lk + 2) * 132 + lr] = a0.z;
        as[(lk + 3) * 132 + lr] = a0.w;
        as[(lk + 8) * 132 + lr] = a1.x;
        as[(lk + 9) * 132 + lr] = a1.y;
        as[(lk + 10) * 132 + lr] = a1.z;
        as[(lk + 11) * 132 + lr] = a1.w;
        bs[(lk + 0) * 132 + lr] = b0.x;
        bs[(lk + 1) * 132 + lr] = b0.y;
        bs[(lk + 2) * 132 + lr] = b0.z;
        bs[(lk + 3) * 132 + lr] = b0.w;
        bs[(lk + 8) * 132 + lr] = b1.x;
        bs[(lk + 9) * 132 + lr] = b1.y;
        bs[(lk + 10) * 132 + lr] = b1.z;
        bs[(lk + 11) * 132 + lr] = b1.w;
        __syncthreads();

        if (c + 1 < NCH) {
            const int kb = (c + 1) << 4;
            a0 = *(const float4*)(Ap + kb);
            a1 = *(const float4*)(Ap + kb + 8);
            b0 = *(const float4*)(Bp + kb);
            b1 = *(const float4*)(Bp + kb + 8);
        }

#pragma unroll
        for (int kk = 0; kk < 16; kk++) {
            float a[8], b[8];
            *(float4*)(a)     = *(const float4*)&as[kk * 132 + (ty << 3)];
            *(float4*)(a + 4) = *(const float4*)&as[kk * 132 + (ty << 3) + 4];
            *(float4*)(b)     = *(const float4*)&bs[kk * 132 + (tx << 3)];
            *(float4*)(b + 4) = *(const float4*)&bs[kk * 132 + (tx << 3) + 4];
#pragma unroll
            for (int i = 0; i < 8; i++)
#pragma unroll
                for (int j = 0; j < 8; j++)
                    acc[i][j] = fmaf(a[i], b[j], acc[i][j]);
        }
    }

    if (MODE == 2) {
#pragma unroll
        for (int i = 0; i < 8; i++) {
            float* crow = C + (size_t)(bm + (ty << 3) + i) * N + bn + (tx << 3);
            *(float4*)(crow)     = make_float4(acc[i][0], acc[i][1], acc[i][2], acc[i][3]);
            *(float4*)(crow + 4) = make_float4(acc[i][4], acc[i][5], acc[i][6], acc[i][7]);
        }
    } else {
        // QKV scatter with fused RoPE on q/k parts
        const int part = bn >> 11;
        const int h = (bn >> 7) & 15;
        const int dkbase = (bn & 127) + (tx << 3);   // even
        float* dst = (part == 0) ? g_q : ((part == 1) ? g_k : g_v);
#pragma unroll
        for (int i = 0; i < 8; i++) {
            int m = bm + (ty << 3) + i;
            int b = m >> 11;
            int s = m & (S_LEN - 1);
            if (part < 2) {
                int pb = (s << 6) + (dkbase >> 1);
#pragma unroll
                for (int t = 0; t < 4; t++) {
                    float cs = g_cos[pb + t];
                    float sn = g_sin[pb + t];
                    float e = acc[i][2 * t], o = acc[i][2 * t + 1];
                    acc[i][2 * t]     = e * cs - o * sn;
                    acc[i][2 * t + 1] = e * sn + o * cs;
                }
            }
            float* row = dst + (((size_t)(b * NHEADS + h) * S_LEN + s) << 7) + dkbase;
            *(float4*)(row)     = make_float4(acc[i][0], acc[i][1], acc[i][2], acc[i][3]);
            *(float4*)(row + 4) = make_float4(acc[i][4], acc[i][5], acc[i][6], acc[i][7]);
        }
    }
}

// ---------------------------------------------------------------------------
// Flash attention (causal, fp32) with cp.async double-buffered K/V tiles.
// Block = one (bh, q-tile of 64 rows). 256 threads as 16x16.
// Q is pre-scaled by 1/sqrt(dk) at load. Heavy tiles launch first.
// ---------------------------------------------------------------------------
#define TILE_F   (64 * 132)                       // floats per 64x128 tile (+pad)
#define ATTN_SMEM_FLOATS (5 * TILE_F + 64 * 68)   // Q + 2K + 2V + P

__global__ void __launch_bounds__(256)
attn_kernel() {
    extern __shared__ float smf[];
    float* Qs  = smf;
    float* Ksb[2] = { smf + 1 * TILE_F, smf + 2 * TILE_F };
    float* Vsb[2] = { smf + 3 * TILE_F, smf + 4 * TILE_F };
    float* Ps  = smf + 5 * TILE_F;

    const int qt = gridDim.x - 1 - blockIdx.x;   // heavy tiles first
    const int bh = blockIdx.y;
    const size_t base = (size_t)bh * S_LEN * DKH;
    const float* qp = g_q + base + ((size_t)qt << 6) * DKH;
    const float* kp = g_k + base;
    const float* vp = g_v + base;

    const int tid = threadIdx.x;
    const int tx = tid & 15, ty = tid >> 4;
    const int r0 = ty << 2;
    const int c0 = tx << 2;
    const int cv = tx << 3;

    const uint32_t sb = smem_to_u32(smf);
    const uint32_t ks_addr[2] = { sb + 1 * TILE_F * 4, sb + 2 * TILE_F * 4 };
    const uint32_t vs_addr[2] = { sb + 3 * TILE_F * 4, sb + 4 * TILE_F * 4 };

    // Q tile load, pre-scaled
    const float scale = 0.08838834764831845f;  // 1/sqrt(128)
    for (int i = tid; i < 64 * 32; i += 256) {
        int r = i >> 5, c4 = (i & 31) << 2;
        float4 v = *(const float4*)&qp[r * 128 + c4];
        Qs[r * 132 + c4 + 0] = v.x * scale;
        Qs[r * 132 + c4 + 1] = v.y * scale;
        Qs[r * 132 + c4 + 2] = v.z * scale;
        Qs[r * 132 + c4 + 3] = v.w * scale;
    }

    // prologue: async-load tile 0 into buffer 0
    {
        const char* kt = (const char*)(kp);
        const char* vt = (const char*)(vp);
#pragma unroll
        for (int p = 0; p < 8; p++) {
            int idx = tid + (p << 8);
            int r = idx >> 5;
            int c16 = (idx & 31) << 4;
            cp_async16(ks_addr[0] + r * 528 + c16, kt + r * 512 + c16);
            cp_async16(vs_addr[0] + r * 528 + c16, vt + r * 512 + c16);
        }
        CP_COMMIT();
    }

    float o[4][8];
#pragma unroll
    for (int i = 0; i < 4; i++)
#pragma unroll
        for (int c = 0; c < 8; c++) o[i][c] = 0.0f;
    float mi[4] = {-INFINITY, -INFINITY, -INFINITY, -INFINITY};
    float li[4] = {0.0f, 0.0f, 0.0f, 0.0f};

    for (int j = 0; j <= qt; j++) {
        const int buf = j & 1;
        __syncthreads();   // all reads of buf^1 (prefetch target) are done

        if (j < qt) {
            const char* kt = (const char*)(kp + ((size_t)(j + 1) << 6) * DKH);
            const char* vt = (const char*)(vp + ((size_t)(j + 1) << 6) * DKH);
#pragma unroll
            for (int p = 0; p < 8; p++) {
                int idx = tid + (p << 8);
                int r = idx >> 5;
                int c16 = (idx & 31) << 4;
                cp_async16(ks_addr[buf ^ 1] + r * 528 + c16, kt + r * 512 + c16);
                cp_async16(vs_addr[buf ^ 1] + r * 528 + c16, vt + r * 512 + c16);
            }
            CP_COMMIT();
            CP_WAIT(1);    // tile j complete (j+1 may be in flight)
        } else {
            CP_WAIT(0);
        }
        __syncthreads();   // tile j visible to all threads

        const float* Ks = Ksb[buf];
        const float* Vs = Vsb[buf];

        // S = Q*K^T (64x64, over dk=128)
        float s[4][4];
#pragma unroll
        for (int i = 0; i < 4; i++)
#pragma unroll
            for (int ii = 0; ii < 4; ii++) s[i][ii] = 0.0f;

#pragma unroll 4
        for (int k4 = 0; k4 < 32; k4++) {
            float q[4][4], kv[4][4];
#pragma unroll
            for (int i = 0; i < 4; i++)
                *(float4*)q[i] = *(const float4*)&Qs[(r0 + i) * 132 + (k4 << 2)];
#pragma unroll
            for (int ii = 0; ii < 4; ii++)
                *(float4*)kv[ii] = *(const float4*)&Ks[(c0 + ii) * 132 + (k4 << 2)];
#pragma unroll
            for (int i = 0; i < 4; i++)
#pragma unroll
                for (int ii = 0; ii < 4; ii++)
#pragma unroll
                    for (int t = 0; t < 4; t++)
                        s[i][ii] = fmaf(q[i][t], kv[ii][t], s[i][ii]);
        }

        // online softmax per row
#pragma unroll
        for (int i = 0; i < 4; i++) {
            float sv[4];
#pragma unroll
            for (int ii = 0; ii < 4; ii++) {
                float v = s[i][ii];
                if (j == qt && (c0 + ii) > (r0 + i)) v = -1e30f;
                sv[ii] = v;
            }
            float rm = fmaxf(fmaxf(sv[0], sv[1]), fmaxf(sv[2], sv[3]));
#pragma unroll
            for (int off = 8; off >= 1; off >>= 1)
                rm = fmaxf(rm, __shfl_xor_sync(0xffffffffu, rm, off));
            float mn = fmaxf(mi[i], rm);
            float al = __expf(mi[i] - mn);
            float rs = 0.0f;
#pragma unroll
            for (int ii = 0; ii < 4; ii++) {
                float p = __expf(sv[ii] - mn);
                sv[ii] = p;
                rs += p;
            }
#pragma unroll
            for (int off = 8; off >= 1; off >>= 1)
                rs += __shfl_xor_sync(0xffffffffu, rs, off);
            li[i] = li[i] * al + rs;
            mi[i] = mn;
#pragma unroll
            for (int c = 0; c < 8; c++) o[i][c] *= al;
            *(float4*)&Ps[(r0 + i) * 68 + c0] = make_float4(sv[0], sv[1], sv[2], sv[3]);
        }
        __syncthreads();

        // O += P * V
#pragma unroll 4
        for (int jj4 = 0; jj4 < 16; jj4++) {
            float p[4][4];
#pragma unroll
            for (int i = 0; i < 4; i++)
                *(float4*)p[i] = *(const float4*)&Ps[(r0 + i) * 68 + (jj4 << 2)];
#pragma unroll
            for (int t = 0; t < 4; t++) {
                int jj = (jj4 << 2) + t;
                float v[8];
                *(float4*)(v)     = *(const float4*)&Vs[jj * 132 + cv];
                *(float4*)(v + 4) = *(const float4*)&Vs[jj * 132 + cv + 4];
#pragma unroll
                for (int i = 0; i < 4; i++)
#pragma unroll
                    for (int c = 0; c < 8; c++)
                        o[i][c] = fmaf(p[i][t], v[c], o[i][c]);
            }
        }
    }

    // epilogue: normalize, write fp32 to g_attn [B,S,D] with D = h*128+dk
    const int b = bh >> 4, h = bh & 15;
#pragma unroll
    for (int i = 0; i < 4; i++) {
        float inv = 1.0f / li[i];
        int srow = (qt << 6) + r0 + i;
        float* orow = g_attn + (((size_t)(b * S_LEN + srow)) << 11) + (h << 7) + cv;
        *(float4*)(orow)     = make_float4(o[i][0] * inv, o[i][1] * inv, o[i][2] * inv, o[i][3] * inv);
        *(float4*)(orow + 4) = make_float4(o[i][4] * inv, o[i][5] * inv, o[i][6] * inv, o[i][7] * inv);
    }
}

// ---------------------------------------------------------------------------
// kernel_launch
// ---------------------------------------------------------------------------
extern "C" void kernel_launch(void* const* d_in, const int* in_sizes, int n_in,
                              void* d_out, int out_size) {
    const float* x     = (const float*)d_in[0];
    const float* w_qkv = (const float*)d_in[1];
    const float* w_out = (const float*)d_in[2];
    float* out = (float*)d_out;

    cudaFuncSetAttribute(attn_kernel, cudaFuncAttributeMaxDynamicSharedMemorySize,
                         ATTN_SMEM_FLOATS * (int)sizeof(float));

    // RoPE tables (needed by QKV epilogue)
    rope_tables_kernel<<<(S_LEN * (DKH / 2) + 255) / 256, 256>>>();

    // QKV projection with fused RoPE, scatter into g_q/g_k/g_v
    sgemm16_nt<1><<<dim3(E3 / 128, MROWS / 128), 256>>>(x, w_qkv, nullptr,
                                                        MROWS, E3, KDIM);

    // causal flash attention (cp.async double-buffered) -> g_attn
    attn_kernel<<<dim3(S_LEN / 64, BHN), 256,
                  ATTN_SMEM_FLOATS * (int)sizeof(float)>>>();

    // output projection
    sgemm16_nt<2><<<dim3(DMODEL / 128, MROWS / 128), 256>>>(nullptr, w_out, out,
                                                            MROWS, DMODEL, KDIM);
}

// round 11
// speedup vs baseline: 10.1405x; 1.3637x over previous
#include <cuda_runtime.h>
#include <math.h>
#include <stdint.h>

// Problem constants
#define S_LEN   2048
#define DMODEL  2048
#define NHEADS  16
#define DKH     128
#define BATCH   4
#define BHN     (BATCH * NHEADS)   // 64
#define E3      (3 * DMODEL)       // 6144
#define MROWS   (BATCH * S_LEN)    // 8192
#define KDIM    DMODEL             // 2048

// ---------------------------------------------------------------------------
// Scratch (static device globals: allocation-free rule)
// ---------------------------------------------------------------------------
__device__ __align__(256) float g_q[BHN * S_LEN * DKH];
__device__ __align__(256) float g_k[BHN * S_LEN * DKH];
__device__ __align__(256) float g_v[BHN * S_LEN * DKH];
__device__ __align__(256) float g_attn[BATCH * S_LEN * DMODEL];
__device__ __align__(256) float g_cos[S_LEN * (DKH / 2)];
__device__ __align__(256) float g_sin[S_LEN * (DKH / 2)];

// ---------------------------------------------------------------------------
// RoPE tables (fp64 for accuracy)
// ---------------------------------------------------------------------------
__global__ void rope_tables_kernel() {
    int idx = blockIdx.x * blockDim.x + threadIdx.x;
    if (idx >= S_LEN * (DKH / 2)) return;
    int i = idx % (DKH / 2);
    int s = idx / (DKH / 2);
    double inv = exp(-((double)(2 * i) / (double)DKH) * log(10000.0));
    double ang = (double)s * inv;
    g_cos[idx] = (float)cos(ang);
    g_sin[idx] = (float)sin(ang);
}

// ---------------------------------------------------------------------------
// FFMA SGEMM  C[M,N] = A[M,K] * B[N,K]^T   (R1-proven k8 loop)
// Conflict-free B-column ownership: thread owns cols {4tx..4tx+3, 64+4tx..+3}.
// MODE 1: QKV -> scatter g_q/g_k/g_v with RoPE fused on q,k parts.
// MODE 2: out-proj (A = g_attn) -> row-major C.
// ---------------------------------------------------------------------------
template <int MODE>
__global__ void __launch_bounds__(256, 2)
sgemm_nt(const float* __restrict__ A, const float* __restrict__ Bw,
         float* __restrict__ C, int M, int N, int K) {
    __shared__ float As[8 * 132];
    __shared__ float Bs[8 * 132];

    const int bm = blockIdx.y << 7;
    const int bn = blockIdx.x << 7;
    const int tid = threadIdx.x;
    const int tx = tid & 15, ty = tid >> 4;

    const float* Aarr = (MODE == 2) ? g_attn : A;
    const int lr = tid >> 1;
    const int lk = (tid & 1) << 2;
    const float* Ap = Aarr + (size_t)(bm + lr) * K + lk;
    const float* Bp = Bw + (size_t)(bn + lr) * K + lk;

    float acc[8][8];
#pragma unroll
    for (int i = 0; i < 8; i++)
#pragma unroll
        for (int j = 0; j < 8; j++) acc[i][j] = 0.0f;

    float4 af = *(const float4*)Ap;
    float4 bf = *(const float4*)Bp;

    for (int k0 = 0; k0 < K; k0 += 8) {
        __syncthreads();
        As[(lk + 0) * 132 + lr] = af.x;
        As[(lk + 1) * 132 + lr] = af.y;
        As[(lk + 2) * 132 + lr] = af.z;
        As[(lk + 3) * 132 + lr] = af.w;
        Bs[(lk + 0) * 132 + lr] = bf.x;
        Bs[(lk + 1) * 132 + lr] = bf.y;
        Bs[(lk + 2) * 132 + lr] = bf.z;
        Bs[(lk + 3) * 132 + lr] = bf.w;
        __syncthreads();
        if (k0 + 8 < K) {
            af = *(const float4*)(Ap + k0 + 8);
            bf = *(const float4*)(Bp + k0 + 8);
        }
#pragma unroll
        for (int kk = 0; kk < 8; kk++) {
            float a[8], b[8];
            *(float4*)(a)     = *(const float4*)&As[kk * 132 + (ty << 3)];
            *(float4*)(a + 4) = *(const float4*)&As[kk * 132 + (ty << 3) + 4];
            // conflict-free: 16B stride across phase lanes
            *(float4*)(b)     = *(const float4*)&Bs[kk * 132 + (tx << 2)];
            *(float4*)(b + 4) = *(const float4*)&Bs[kk * 132 + (tx << 2) + 64];
#pragma unroll
            for (int i = 0; i < 8; i++)
#pragma unroll
                for (int j = 0; j < 8; j++)
                    acc[i][j] = fmaf(a[i], b[j], acc[i][j]);
        }
    }

    const int cA = tx << 2;        // cols cA..cA+3 within the 128-wide n-tile
    const int cB = cA + 64;        // cols cB..cB+3
    if (MODE == 2) {
#pragma unroll
        for (int i = 0; i < 8; i++) {
            float* crow = C + (size_t)(bm + (ty << 3) + i) * N + bn;
            *(float4*)(crow + cA) = make_float4(acc[i][0], acc[i][1], acc[i][2], acc[i][3]);
            *(float4*)(crow + cB) = make_float4(acc[i][4], acc[i][5], acc[i][6], acc[i][7]);
        }
    } else {
        const int part = bn >> 11;
        const int h = (bn >> 7) & 15;
        float* dst = (part == 0) ? g_q : ((part == 1) ? g_k : g_v);
#pragma unroll
        for (int i = 0; i < 8; i++) {
            int m = bm + (ty << 3) + i;
            int b = m >> 11;
            int s = m & (S_LEN - 1);
            if (part < 2) {
                // RoPE: cols cA..cA+3 = pairs (cA>>1), (cA>>1)+1 ; cols cB.. = +32
                int pb = (s << 6) + (cA >> 1);
#pragma unroll
                for (int t = 0; t < 2; t++) {
                    float cs = g_cos[pb + t], sn = g_sin[pb + t];
                    float e = acc[i][2 * t], o = acc[i][2 * t + 1];
                    acc[i][2 * t]     = e * cs - o * sn;
                    acc[i][2 * t + 1] = e * sn + o * cs;
                    float cs2 = g_cos[pb + 32 + t], sn2 = g_sin[pb + 32 + t];
                    float e2 = acc[i][4 + 2 * t], o2 = acc[i][5 + 2 * t];
                    acc[i][4 + 2 * t] = e2 * cs2 - o2 * sn2;
                    acc[i][5 + 2 * t] = e2 * sn2 + o2 * cs2;
                }
            }
            float* row = dst + (((size_t)(b * NHEADS + h) * S_LEN + s) << 7);
            *(float4*)(row + cA) = make_float4(acc[i][0], acc[i][1], acc[i][2], acc[i][3]);
            *(float4*)(row + cB) = make_float4(acc[i][4], acc[i][5], acc[i][6], acc[i][7]);
        }
    }
}

// ---------------------------------------------------------------------------
// Flash attention (causal, fp32) -> g_attn.  R1 structure with conflict-free
// smem column ownership:
//   QK score cols per thread: {tx, tx+16, tx+32, tx+48}  (K rows stride-1/lane)
//   Output cols per thread:   {4tx..4tx+3, 64+4tx..+3}   (V 16B-stride/lane)
// Q pre-scaled at load. Heavy q-tiles launch first.
// ---------------------------------------------------------------------------
#define ATTN_SMEM_FLOATS (3 * 64 * 132 + 64 * 68)

__global__ void __launch_bounds__(256)
attn_kernel() {
    extern __shared__ float smf[];
    float* Qs = smf;
    float* Ks = smf + 64 * 132;
    float* Vs = smf + 2 * 64 * 132;
    float* Ps = smf + 3 * 64 * 132;

    const int qt = gridDim.x - 1 - blockIdx.x;   // heavy tiles first
    const int bh = blockIdx.y;
    const size_t base = (size_t)bh * S_LEN * DKH;
    const float* qp = g_q + base + ((size_t)qt << 6) * DKH;
    const float* kp = g_k + base;
    const float* vp = g_v + base;

    const int tid = threadIdx.x;
    const int tx = tid & 15, ty = tid >> 4;
    const int r0 = ty << 2;          // 4 score rows per thread
    const int cA = tx << 2;          // output col group A
    const int cB = cA + 64;          // output col group B

    // Q tile load, pre-scaled by 1/sqrt(dk)
    const float scale = 0.08838834764831845f;
    for (int i = tid; i < 64 * 32; i += 256) {
        int r = i >> 5, c4 = (i & 31) << 2;
        float4 v = *(const float4*)&qp[r * 128 + c4];
        Qs[r * 132 + c4 + 0] = v.x * scale;
        Qs[r * 132 + c4 + 1] = v.y * scale;
        Qs[r * 132 + c4 + 2] = v.z * scale;
        Qs[r * 132 + c4 + 3] = v.w * scale;
    }

    float o[4][8];
#pragma unroll
    for (int i = 0; i < 4; i++)
#pragma unroll
        for (int c = 0; c < 8; c++) o[i][c] = 0.0f;
    float mi[4] = {-INFINITY, -INFINITY, -INFINITY, -INFINITY};
    float li[4] = {0.0f, 0.0f, 0.0f, 0.0f};

    for (int j = 0; j <= qt; j++) {
        __syncthreads();
        const float* kt = kp + ((size_t)j << 6) * DKH;
        const float* vt = vp + ((size_t)j << 6) * DKH;
        for (int i = tid; i < 64 * 32; i += 256) {
            int r = i >> 5, c4 = (i & 31) << 2;
            *(float4*)&Ks[r * 132 + c4] = *(const float4*)&kt[r * 128 + c4];
            *(float4*)&Vs[r * 132 + c4] = *(const float4*)&vt[r * 128 + c4];
        }
        __syncthreads();

        // S = Q * K^T ; thread's score cols: tx + 16*ii
        float s[4][4];
#pragma unroll
        for (int i = 0; i < 4; i++)
#pragma unroll
            for (int ii = 0; ii < 4; ii++) s[i][ii] = 0.0f;

#pragma unroll 4
        for (int k4 = 0; k4 < 32; k4++) {
            float q[4][4], kv[4][4];
#pragma unroll
            for (int i = 0; i < 4; i++)
                *(float4*)q[i] = *(const float4*)&Qs[(r0 + i) * 132 + (k4 << 2)];
#pragma unroll
            for (int ii = 0; ii < 4; ii++)
                *(float4*)kv[ii] = *(const float4*)&Ks[(tx + (ii << 4)) * 132 + (k4 << 2)];
#pragma unroll
            for (int i = 0; i < 4; i++)
#pragma unroll
                for (int ii = 0; ii < 4; ii++)
#pragma unroll
                    for (int t = 0; t < 4; t++)
                        s[i][ii] = fmaf(q[i][t], kv[ii][t], s[i][ii]);
        }

        // online softmax per row (row owned by the 16 tx lanes)
#pragma unroll
        for (int i = 0; i < 4; i++) {
            float sv[4];
#pragma unroll
            for (int ii = 0; ii < 4; ii++) {
                float v = s[i][ii];
                if (j == qt && (tx + (ii << 4)) > (r0 + i)) v = -1e30f;
                sv[ii] = v;
            }
            float rm = fmaxf(fmaxf(sv[0], sv[1]), fmaxf(sv[2], sv[3]));
#pragma unroll
            for (int off = 8; off >= 1; off >>= 1)
                rm = fmaxf(rm, __shfl_xor_sync(0xffffffffu, rm, off));
            float mn = fmaxf(mi[i], rm);
            float al = __expf(mi[i] - mn);
            float rs = 0.0f;
#pragma unroll
            for (int ii = 0; ii < 4; ii++) {
                float p = __expf(sv[ii] - mn);
                sv[ii] = p;
                rs += p;
            }
#pragma unroll
            for (int off = 8; off >= 1; off >>= 1)
                rs += __shfl_xor_sync(0xffffffffu, rs, off);
            li[i] = li[i] * al + rs;
            mi[i] = mn;
#pragma unroll
            for (int c = 0; c < 8; c++) o[i][c] *= al;
#pragma unroll
            for (int ii = 0; ii < 4; ii++)
                Ps[(r0 + i) * 68 + tx + (ii << 4)] = sv[ii];
        }
        __syncthreads();

        // O += P * V ; thread's output cols: cA..cA+3, cB..cB+3
#pragma unroll 4
        for (int jj4 = 0; jj4 < 16; jj4++) {
            float p[4][4];
#pragma unroll
            for (int i = 0; i < 4; i++)
                *(float4*)p[i] = *(const float4*)&Ps[(r0 + i) * 68 + (jj4 << 2)];
#pragma unroll
            for (int t = 0; t < 4; t++) {
                int jj = (jj4 << 2) + t;
                float v[8];
                *(float4*)(v)     = *(const float4*)&Vs[jj * 132 + cA];
                *(float4*)(v + 4) = *(const float4*)&Vs[jj * 132 + cB];
#pragma unroll
                for (int i = 0; i < 4; i++)
#pragma unroll
                    for (int c = 0; c < 8; c++)
                        o[i][c] = fmaf(p[i][t], v[c], o[i][c]);
            }
        }
    }

    // epilogue: normalize, write fp32 to g_attn [B,S,D] with D = h*128+dk
    const int b = bh >> 4, h = bh & 15;
#pragma unroll
    for (int i = 0; i < 4; i++) {
        float inv = 1.0f / li[i];
        int srow = (qt << 6) + r0 + i;
        float* orow = g_attn + (((size_t)(b * S_LEN + srow)) << 11) + (h << 7);
        *(float4*)(orow + cA) = make_float4(o[i][0] * inv, o[i][1] * inv,
                                            o[i][2] * inv, o[i][3] * inv);
        *(float4*)(orow + cB) = make_float4(o[i][4] * inv, o[i][5] * inv,
                                            o[i][6] * inv, o[i][7] * inv);
    }
}

// ---------------------------------------------------------------------------
// kernel_launch
// ---------------------------------------------------------------------------
extern "C" void kernel_launch(void* const* d_in, const int* in_sizes, int n_in,
                              void* d_out, int out_size) {
    const float* x     = (const float*)d_in[0];
    const float* w_qkv = (const float*)d_in[1];
    const float* w_out = (const float*)d_in[2];
    float* out = (float*)d_out;

    cudaFuncSetAttribute(attn_kernel, cudaFuncAttributeMaxDynamicSharedMemorySize,
                         ATTN_SMEM_FLOATS * (int)sizeof(float));

    // RoPE tables (consumed by the QKV epilogue)
    rope_tables_kernel<<<(S_LEN * (DKH / 2) + 255) / 256, 256>>>();

    // QKV projection with fused RoPE, scatter into g_q/g_k/g_v
    sgemm_nt<1><<<dim3(E3 / 128, MROWS / 128), 256>>>(x, w_qkv, nullptr,
                                                      MROWS, E3, KDIM);

    // causal flash attention -> g_attn
    attn_kernel<<<dim3(S_LEN / 64, BHN), 256,
                  ATTN_SMEM_FLOATS * (int)sizeof(float)>>>();

    // output projection
    sgemm_nt<2><<<dim3(DMODEL / 128, MROWS / 128), 256>>>(nullptr, w_out, out,
                                                          MROWS, DMODEL, KDIM);
}

// round 12
// speedup vs baseline: 10.6626x; 1.0515x over previous
#include <cuda_runtime.h>
#include <math.h>
#include <stdint.h>

// Problem constants
#define S_LEN   2048
#define DMODEL  2048
#define NHEADS  16
#define DKH     128
#define BATCH   4
#define BHN     (BATCH * NHEADS)   // 64
#define E3      (3 * DMODEL)       // 6144
#define MROWS   (BATCH * S_LEN)    // 8192
#define KDIM    DMODEL             // 2048

// ---------------------------------------------------------------------------
// Scratch (static device globals: allocation-free rule)
// ---------------------------------------------------------------------------
__device__ __align__(256) float g_q[BHN * S_LEN * DKH];
__device__ __align__(256) float g_k[BHN * S_LEN * DKH];
__device__ __align__(256) float g_v[BHN * S_LEN * DKH];
__device__ __align__(256) float g_attn[BATCH * S_LEN * DMODEL];
__device__ __align__(256) float g_cos[S_LEN * (DKH / 2)];
__device__ __align__(256) float g_sin[S_LEN * (DKH / 2)];

// ---------------------------------------------------------------------------
// RoPE tables (fp64 for accuracy)
// ---------------------------------------------------------------------------
__global__ void rope_tables_kernel() {
    int idx = blockIdx.x * blockDim.x + threadIdx.x;
    if (idx >= S_LEN * (DKH / 2)) return;
    int i = idx % (DKH / 2);
    int s = idx / (DKH / 2);
    double inv = exp(-((double)(2 * i) / (double)DKH) * log(10000.0));
    double ang = (double)s * inv;
    g_cos[idx] = (float)cos(ang);
    g_sin[idx] = (float)sin(ang);
}

// ---------------------------------------------------------------------------
// FFMA SGEMM  C[M,N] = A[M,K] * B[N,K]^T   (R11-validated, conflict-free)
// MODE 1: QKV -> scatter g_q/g_k/g_v with RoPE fused on q,k parts.
// MODE 2: out-proj (A = g_attn) -> row-major C.
// ---------------------------------------------------------------------------
template <int MODE>
__global__ void __launch_bounds__(256, 2)
sgemm_nt(const float* __restrict__ A, const float* __restrict__ Bw,
         float* __restrict__ C, int M, int N, int K) {
    __shared__ float As[8 * 132];
    __shared__ float Bs[8 * 132];

    const int bm = blockIdx.y << 7;
    const int bn = blockIdx.x << 7;
    const int tid = threadIdx.x;
    const int tx = tid & 15, ty = tid >> 4;

    const float* Aarr = (MODE == 2) ? g_attn : A;
    const int lr = tid >> 1;
    const int lk = (tid & 1) << 2;
    const float* Ap = Aarr + (size_t)(bm + lr) * K + lk;
    const float* Bp = Bw + (size_t)(bn + lr) * K + lk;

    float acc[8][8];
#pragma unroll
    for (int i = 0; i < 8; i++)
#pragma unroll
        for (int j = 0; j < 8; j++) acc[i][j] = 0.0f;

    float4 af = *(const float4*)Ap;
    float4 bf = *(const float4*)Bp;

    for (int k0 = 0; k0 < K; k0 += 8) {
        __syncthreads();
        As[(lk + 0) * 132 + lr] = af.x;
        As[(lk + 1) * 132 + lr] = af.y;
        As[(lk + 2) * 132 + lr] = af.z;
        As[(lk + 3) * 132 + lr] = af.w;
        Bs[(lk + 0) * 132 + lr] = bf.x;
        Bs[(lk + 1) * 132 + lr] = bf.y;
        Bs[(lk + 2) * 132 + lr] = bf.z;
        Bs[(lk + 3) * 132 + lr] = bf.w;
        __syncthreads();
        if (k0 + 8 < K) {
            af = *(const float4*)(Ap + k0 + 8);
            bf = *(const float4*)(Bp + k0 + 8);
        }
#pragma unroll
        for (int kk = 0; kk < 8; kk++) {
            float a[8], b[8];
            *(float4*)(a)     = *(const float4*)&As[kk * 132 + (ty << 3)];
            *(float4*)(a + 4) = *(const float4*)&As[kk * 132 + (ty << 3) + 4];
            *(float4*)(b)     = *(const float4*)&Bs[kk * 132 + (tx << 2)];
            *(float4*)(b + 4) = *(const float4*)&Bs[kk * 132 + (tx << 2) + 64];
#pragma unroll
            for (int i = 0; i < 8; i++)
#pragma unroll
                for (int j = 0; j < 8; j++)
                    acc[i][j] = fmaf(a[i], b[j], acc[i][j]);
        }
    }

    const int cA = tx << 2;
    const int cB = cA + 64;
    if (MODE == 2) {
#pragma unroll
        for (int i = 0; i < 8; i++) {
            float* crow = C + (size_t)(bm + (ty << 3) + i) * N + bn;
            *(float4*)(crow + cA) = make_float4(acc[i][0], acc[i][1], acc[i][2], acc[i][3]);
            *(float4*)(crow + cB) = make_float4(acc[i][4], acc[i][5], acc[i][6], acc[i][7]);
        }
    } else {
        const int part = bn >> 11;
        const int h = (bn >> 7) & 15;
        float* dst = (part == 0) ? g_q : ((part == 1) ? g_k : g_v);
#pragma unroll
        for (int i = 0; i < 8; i++) {
            int m = bm + (ty << 3) + i;
            int b = m >> 11;
            int s = m & (S_LEN - 1);
            if (part < 2) {
                int pb = (s << 6) + (cA >> 1);
#pragma unroll
                for (int t = 0; t < 2; t++) {
                    float cs = g_cos[pb + t], sn = g_sin[pb + t];
                    float e = acc[i][2 * t], o = acc[i][2 * t + 1];
                    acc[i][2 * t]     = e * cs - o * sn;
                    acc[i][2 * t + 1] = e * sn + o * cs;
                    float cs2 = g_cos[pb + 32 + t], sn2 = g_sin[pb + 32 + t];
                    float e2 = acc[i][4 + 2 * t], o2 = acc[i][5 + 2 * t];
                    acc[i][4 + 2 * t] = e2 * cs2 - o2 * sn2;
                    acc[i][5 + 2 * t] = e2 * sn2 + o2 * cs2;
                }
            }
            float* row = dst + (((size_t)(b * NHEADS + h) * S_LEN + s) << 7);
            *(float4*)(row + cA) = make_float4(acc[i][0], acc[i][1], acc[i][2], acc[i][3]);
            *(float4*)(row + cB) = make_float4(acc[i][4], acc[i][5], acc[i][6], acc[i][7]);
        }
    }
}

// ---------------------------------------------------------------------------
// Flash attention (causal, fp32) -> g_attn.
// Shared K/V smem buffer -> 83 KB -> 2 CTAs/SM for latency hiding.
// Conflict-free mappings (R11): QK cols {tx,tx+16,tx+32,tx+48};
// output cols {4tx..4tx+3, 64+4tx..+3}. Q pre-scaled; heavy tiles first.
// ---------------------------------------------------------------------------
#define ATTN_SMEM_FLOATS (2 * 64 * 132 + 64 * 68)   // Q + KV + P = 21248

__global__ void __launch_bounds__(256, 2)
attn_kernel() {
    extern __shared__ float smf[];
    float* Qs  = smf;
    float* KVs = smf + 64 * 132;
    float* Ps  = smf + 2 * 64 * 132;

    const int qt = gridDim.x - 1 - blockIdx.x;   // heavy tiles first
    const int bh = blockIdx.y;
    const size_t base = (size_t)bh * S_LEN * DKH;
    const float* qp = g_q + base + ((size_t)qt << 6) * DKH;
    const float* kp = g_k + base;
    const float* vp = g_v + base;

    const int tid = threadIdx.x;
    const int tx = tid & 15, ty = tid >> 4;
    const int r0 = ty << 2;          // 4 score rows per thread
    const int cA = tx << 2;          // output col group A
    const int cB = cA + 64;          // output col group B

    // Q tile load, pre-scaled by 1/sqrt(dk)
    const float scale = 0.08838834764831845f;
    for (int i = tid; i < 64 * 32; i += 256) {
        int r = i >> 5, c4 = (i & 31) << 2;
        float4 v = *(const float4*)&qp[r * 128 + c4];
        Qs[r * 132 + c4 + 0] = v.x * scale;
        Qs[r * 132 + c4 + 1] = v.y * scale;
        Qs[r * 132 + c4 + 2] = v.z * scale;
        Qs[r * 132 + c4 + 3] = v.w * scale;
    }

    float o[4][8];
#pragma unroll
    for (int i = 0; i < 4; i++)
#pragma unroll
        for (int c = 0; c < 8; c++) o[i][c] = 0.0f;
    float mi[4] = {-INFINITY, -INFINITY, -INFINITY, -INFINITY};
    float li[4] = {0.0f, 0.0f, 0.0f, 0.0f};

    for (int j = 0; j <= qt; j++) {
        // ---- load K tile into shared KV buffer ----
        __syncthreads();   // prior PV reads of KVs (V) complete
        const float* kt = kp + ((size_t)j << 6) * DKH;
        for (int i = tid; i < 64 * 32; i += 256) {
            int r = i >> 5, c4 = (i & 31) << 2;
            *(float4*)&KVs[r * 132 + c4] = *(const float4*)&kt[r * 128 + c4];
        }
        __syncthreads();

        // ---- S = Q * K^T ; thread's score cols: tx + 16*ii ----
        float s[4][4];
#pragma unroll
        for (int i = 0; i < 4; i++)
#pragma unroll
            for (int ii = 0; ii < 4; ii++) s[i][ii] = 0.0f;

#pragma unroll 4
        for (int k4 = 0; k4 < 32; k4++) {
            float q[4][4], kv[4][4];
#pragma unroll
            for (int i = 0; i < 4; i++)
                *(float4*)q[i] = *(const float4*)&Qs[(r0 + i) * 132 + (k4 << 2)];
#pragma unroll
            for (int ii = 0; ii < 4; ii++)
                *(float4*)kv[ii] = *(const float4*)&KVs[(tx + (ii << 4)) * 132 + (k4 << 2)];
#pragma unroll
            for (int i = 0; i < 4; i++)
#pragma unroll
                for (int ii = 0; ii < 4; ii++)
#pragma unroll
                    for (int t = 0; t < 4; t++)
                        s[i][ii] = fmaf(q[i][t], kv[ii][t], s[i][ii]);
        }

        // ---- online softmax per row ----
#pragma unroll
        for (int i = 0; i < 4; i++) {
            float sv[4];
#pragma unroll
            for (int ii = 0; ii < 4; ii++) {
                float v = s[i][ii];
                if (j == qt && (tx + (ii << 4)) > (r0 + i)) v = -1e30f;
                sv[ii] = v;
            }
            float rm = fmaxf(fmaxf(sv[0], sv[1]), fmaxf(sv[2], sv[3]));
#pragma unroll
            for (int off = 8; off >= 1; off >>= 1)
                rm = fmaxf(rm, __shfl_xor_sync(0xffffffffu, rm, off));
            float mn = fmaxf(mi[i], rm);
            float al = __expf(mi[i] - mn);
            float rs = 0.0f;
#pragma unroll
            for (int ii = 0; ii < 4; ii++) {
                float p = __expf(sv[ii] - mn);
                sv[ii] = p;
                rs += p;
            }
#pragma unroll
            for (int off = 8; off >= 1; off >>= 1)
                rs += __shfl_xor_sync(0xffffffffu, rs, off);
            li[i] = li[i] * al + rs;
            mi[i] = mn;
#pragma unroll
            for (int c = 0; c < 8; c++) o[i][c] *= al;
#pragma unroll
            for (int ii = 0; ii < 4; ii++)
                Ps[(r0 + i) * 68 + tx + (ii << 4)] = sv[ii];
        }

        // ---- load V tile into the same KV buffer ----
        __syncthreads();   // all K reads + P writes complete
        const float* vt = vp + ((size_t)j << 6) * DKH;
        for (int i = tid; i < 64 * 32; i += 256) {
            int r = i >> 5, c4 = (i & 31) << 2;
            *(float4*)&KVs[r * 132 + c4] = *(const float4*)&vt[r * 128 + c4];
        }
        __syncthreads();

        // ---- O += P * V ; thread's output cols: cA..cA+3, cB..cB+3 ----
#pragma unroll 4
        for (int jj4 = 0; jj4 < 16; jj4++) {
            float p[4][4];
#pragma unroll
            for (int i = 0; i < 4; i++)
                *(float4*)p[i] = *(const float4*)&Ps[(r0 + i) * 68 + (jj4 << 2)];
#pragma unroll
            for (int t = 0; t < 4; t++) {
                int jj = (jj4 << 2) + t;
                float v[8];
                *(float4*)(v)     = *(const float4*)&KVs[jj * 132 + cA];
                *(float4*)(v + 4) = *(const float4*)&KVs[jj * 132 + cB];
#pragma unroll
                for (int i = 0; i < 4; i++)
#pragma unroll
                    for (int c = 0; c < 8; c++)
                        o[i][c] = fmaf(p[i][t], v[c], o[i][c]);
            }
        }
    }

    // epilogue: normalize, write fp32 to g_attn [B,S,D] with D = h*128+dk
    const int b = bh >> 4, h = bh & 15;
#pragma unroll
    for (int i = 0; i < 4; i++) {
        float inv = 1.0f / li[i];
        int srow = (qt << 6) + r0 + i;
        float* orow = g_attn + (((size_t)(b * S_LEN + srow)) << 11) + (h << 7);
        *(float4*)(orow + cA) = make_float4(o[i][0] * inv, o[i][1] * inv,
                                            o[i][2] * inv, o[i][3] * inv);
        *(float4*)(orow + cB) = make_float4(o[i][4] * inv, o[i][5] * inv,
                                            o[i][6] * inv, o[i][7] * inv);
    }
}

// ---------------------------------------------------------------------------
// kernel_launch
// ---------------------------------------------------------------------------
extern "C" void kernel_launch(void* const* d_in, const int* in_sizes, int n_in,
                              void* d_out, int out_size) {
    const float* x     = (const float*)d_in[0];
    const float* w_qkv = (const float*)d_in[1];
    const float* w_out = (const float*)d_in[2];
    float* out = (float*)d_out;

    cudaFuncSetAttribute(attn_kernel, cudaFuncAttributeMaxDynamicSharedMemorySize,
                         ATTN_SMEM_FLOATS * (int)sizeof(float));

    // RoPE tables (consumed by the QKV epilogue)
    rope_tables_kernel<<<(S_LEN * (DKH / 2) + 255) / 256, 256>>>();

    // QKV projection with fused RoPE, scatter into g_q/g_k/g_v
    sgemm_nt<1><<<dim3(E3 / 128, MROWS / 128), 256>>>(x, w_qkv, nullptr,
                                                      MROWS, E3, KDIM);

    // causal flash attention -> g_attn (2 CTAs/SM)
    attn_kernel<<<dim3(S_LEN / 64, BHN), 256,
                  ATTN_SMEM_FLOATS * (int)sizeof(float)>>>();

    // output projection
    sgemm_nt<2><<<dim3(DMODEL / 128, MROWS / 128), 256>>>(nullptr, w_out, out,
                                                          MROWS, DMODEL, KDIM);
}